// round 3
// baseline (speedup 1.0000x reference)
#include <cuda_runtime.h>
#include <cstdint>

// ---------------------------------------------------------------------------
// FeaStEncoderBlock: two FeaStConv(H=4) residual blocks on a 20000-node,
// 320000-edge graph (+ self loops).
//
// edge_index is int32 (JAX demotes int64 without x64 mode).
//
// Pipeline:
//   1. build dst-CSR (init / histogram / scan / scatter)
//   2. p0 = x@u0  -> ea = exp(p+c), eb = exp(-p)   [softmax factorization]
//   3. g_y = x@W0           (SGEMM 20000x128 @ 128x1024)
//   4. g_h = x@skipW0       (SGEMM 20000x128 @ 128x256)
//   5. aggregate0: g_h = relu(mean_j q.g_y[j] + b0 + g_h + skipb0)
//   6. p1 from g_h -> ea/eb
//   7. g_y = g_h@W1         (SGEMM 20000x256 @ 256x1024)
//   8. aggregate1: out = relu(mean_j q.g_y[j] + b1 + g_h)
//   9. append edge_index passthrough (int32 -> f32 cast)
// ---------------------------------------------------------------------------

#define MAXN 20000
#define MAXE 320000

__device__ __align__(16) float g_y[(size_t)MAXN * 1024];   // 82 MB
__device__ __align__(16) float g_h[(size_t)MAXN * 256];    // 20 MB
__device__ __align__(16) float g_ea[MAXN * 4];
__device__ __align__(16) float g_eb[MAXN * 4];
__device__ int   g_deg[MAXN];
__device__ int   g_cur[MAXN];
__device__ int   g_offs[MAXN + 1];
__device__ int   g_srcs[MAXN + MAXE];

// ---------------------------------------------------------------- CSR build
__global__ void k_init(int n) {
    int i = blockIdx.x * blockDim.x + threadIdx.x;
    if (i < n) { g_deg[i] = 1; g_cur[i] = 0; }   // deg starts at 1 (self loop)
}

__global__ void k_hist(const int* __restrict__ ei, int E, int n) {
    int t = blockIdx.x * blockDim.x + threadIdx.x;
    if (t < E) {
        int d = ei[E + t];                        // dst row
        if (d >= 0 && d < n) atomicAdd(&g_deg[d], 1);
    }
}

// single-block exclusive scan over g_deg[0..n) -> g_offs[0..n]
__global__ void k_scan(int n) {
    __shared__ int sh[1024];
    __shared__ int carry;
    if (threadIdx.x == 0) carry = 0;
    __syncthreads();
    int nchunks = (n + 1023) / 1024;
    for (int chunk = 0; chunk < nchunks; ++chunk) {
        int i = chunk * 1024 + threadIdx.x;
        int v = (i < n) ? g_deg[i] : 0;
        sh[threadIdx.x] = v;
        __syncthreads();
        #pragma unroll
        for (int off = 1; off < 1024; off <<= 1) {
            int t = (threadIdx.x >= off) ? sh[threadIdx.x - off] : 0;
            __syncthreads();
            sh[threadIdx.x] += t;
            __syncthreads();
        }
        int incl = sh[threadIdx.x] + carry;
        if (i < n) g_offs[i + 1] = incl;
        __syncthreads();
        if (threadIdx.x == 1023) carry = incl;
        __syncthreads();
    }
    if (threadIdx.x == 0) g_offs[0] = 0;
}

__global__ void k_fill(const int* __restrict__ ei, int E, int n) {
    int t = blockIdx.x * blockDim.x + threadIdx.x;
    if (t >= E + n) return;
    int s, d;
    if (t < E) { s = ei[t]; d = ei[E + t]; }
    else       { s = d = t - E; }                 // self loop
    if (s < 0 || s >= n || d < 0 || d >= n) return;
    int pos = g_offs[d] + atomicAdd(&g_cur[d], 1);
    g_srcs[pos] = s;
}

// -------------------------------------------- per-node attention projections
// p = x@u ([N,4]); store ea = exp(p+c), eb = exp(-p). One warp per node.
// x_sel: 0 -> external pointer, 1 -> g_h
__global__ void k_nodep(const float* __restrict__ x_ext, int x_sel,
                        const float* __restrict__ u,
                        const float* __restrict__ c, int K, int n) {
    int warp = (blockIdx.x * blockDim.x + threadIdx.x) >> 5;
    int lane = threadIdx.x & 31;
    if (warp >= n) return;
    const float* x = x_sel ? g_h : x_ext;
    const float* xr = x + (size_t)warp * K;
    float a0 = 0.f, a1 = 0.f, a2 = 0.f, a3 = 0.f;
    for (int k = lane; k < K; k += 32) {
        float xv = xr[k];
        float4 uv = ((const float4*)u)[k];        // u row-major [K,4]
        a0 += xv * uv.x; a1 += xv * uv.y; a2 += xv * uv.z; a3 += xv * uv.w;
    }
    #pragma unroll
    for (int off = 16; off; off >>= 1) {
        a0 += __shfl_down_sync(0xffffffffu, a0, off);
        a1 += __shfl_down_sync(0xffffffffu, a1, off);
        a2 += __shfl_down_sync(0xffffffffu, a2, off);
        a3 += __shfl_down_sync(0xffffffffu, a3, off);
    }
    if (lane == 0) {
        float4 ea, eb;
        ea.x = expf(a0 + c[0]); ea.y = expf(a1 + c[1]);
        ea.z = expf(a2 + c[2]); ea.w = expf(a3 + c[3]);
        eb.x = expf(-a0); eb.y = expf(-a1); eb.z = expf(-a2); eb.w = expf(-a3);
        ((float4*)g_ea)[warp] = ea;
        ((float4*)g_eb)[warp] = eb;
    }
}

// ------------------------------------------------------------------- SGEMM
// C[M,N] = A[M,K] @ B[K,N], row-major. 128x128x8 tile, 8x8 per thread.
// a_sel: 0 -> A_ext, 1 -> g_h.   c_sel: 0 -> g_y, 1 -> g_h.
__global__ void __launch_bounds__(256) k_sgemm(const float* __restrict__ A_ext,
                                               int a_sel,
                                               const float* __restrict__ B,
                                               int c_sel,
                                               int M, int N, int K) {
    __shared__ float As[8][128];
    __shared__ float Bs[8][128];
    const float* A = a_sel ? g_h : A_ext;
    float* C = c_sel ? g_h : g_y;

    int tid = threadIdx.x;
    int bx = blockIdx.x, by = blockIdx.y;
    int rowA = by * 128 + (tid >> 1);
    int kA   = (tid & 1) * 4;
    int kB   = tid >> 5;
    int colB = bx * 128 + (tid & 31) * 4;
    int tx = tid & 15, ty = tid >> 4;

    float acc[8][8];
    #pragma unroll
    for (int i = 0; i < 8; i++)
        #pragma unroll
        for (int j = 0; j < 8; j++) acc[i][j] = 0.f;

    for (int k0 = 0; k0 < K; k0 += 8) {
        float4 av = make_float4(0.f, 0.f, 0.f, 0.f);
        if (rowA < M) av = *(const float4*)(A + (size_t)rowA * K + k0 + kA);
        As[kA + 0][tid >> 1] = av.x;
        As[kA + 1][tid >> 1] = av.y;
        As[kA + 2][tid >> 1] = av.z;
        As[kA + 3][tid >> 1] = av.w;
        float4 bv = *(const float4*)(B + (size_t)(k0 + kB) * N + colB);
        *(float4*)&Bs[kB][(tid & 31) * 4] = bv;
        __syncthreads();
        #pragma unroll
        for (int k = 0; k < 8; k++) {
            float af[8], bf[8];
            *(float4*)(af)     = *(const float4*)&As[k][ty * 8];
            *(float4*)(af + 4) = *(const float4*)&As[k][ty * 8 + 4];
            *(float4*)(bf)     = *(const float4*)&Bs[k][tx * 8];
            *(float4*)(bf + 4) = *(const float4*)&Bs[k][tx * 8 + 4];
            #pragma unroll
            for (int i = 0; i < 8; i++)
                #pragma unroll
                for (int j = 0; j < 8; j++)
                    acc[i][j] += af[i] * bf[j];
        }
        __syncthreads();
    }
    #pragma unroll
    for (int i = 0; i < 8; i++) {
        int r = by * 128 + ty * 8 + i;
        if (r < M) {
            float4* cp = (float4*)(C + (size_t)r * N + bx * 128 + tx * 8);
            cp[0] = make_float4(acc[i][0], acc[i][1], acc[i][2], acc[i][3]);
            cp[1] = make_float4(acc[i][4], acc[i][5], acc[i][6], acc[i][7]);
        }
    }
}

// --------------------------------------------------------------- aggregate
// One warp per node. Reads y from g_y, addend from g_h.
// out_sel: 0 -> write g_h, 1 -> write out_ext.
__device__ __forceinline__ float4 fma4(float4 a, float s, float4 v) {
    a.x += s * v.x; a.y += s * v.y; a.z += s * v.z; a.w += s * v.w; return a;
}

__global__ void k_aggregate(const float* __restrict__ b,
                            const float* __restrict__ b2,   // may be null
                            float* __restrict__ out_ext, int out_sel,
                            int n) {
    int warp = (blockIdx.x * blockDim.x + threadIdx.x) >> 5;
    int lane = threadIdx.x & 31;
    if (warp >= n) return;
    int i  = warp;
    int s0 = g_offs[i], s1 = g_offs[i + 1];
    float4 ebi = ((const float4*)g_eb)[i];
    float4 acc0 = make_float4(0.f, 0.f, 0.f, 0.f);
    float4 acc1 = make_float4(0.f, 0.f, 0.f, 0.f);

    for (int e = s0; e < s1; ++e) {
        int j = g_srcs[e];
        float4 a = ((const float4*)g_ea)[j];
        float q0 = a.x * ebi.x, q1 = a.y * ebi.y, q2 = a.z * ebi.z, q3 = a.w * ebi.w;
        float rz = 1.0f / (q0 + q1 + q2 + q3);
        q0 *= rz; q1 *= rz; q2 *= rz; q3 *= rz;
        const float4* yj = (const float4*)(g_y + (size_t)j * 1024);
        acc0 = fma4(acc0, q0, yj[0 * 64 + lane]);
        acc1 = fma4(acc1, q0, yj[0 * 64 + lane + 32]);
        acc0 = fma4(acc0, q1, yj[1 * 64 + lane]);
        acc1 = fma4(acc1, q1, yj[1 * 64 + lane + 32]);
        acc0 = fma4(acc0, q2, yj[2 * 64 + lane]);
        acc1 = fma4(acc1, q2, yj[2 * 64 + lane + 32]);
        acc0 = fma4(acc0, q3, yj[3 * 64 + lane]);
        acc1 = fma4(acc1, q3, yj[3 * 64 + lane + 32]);
    }
    float inv = 1.0f / (float)(s1 - s0 > 0 ? s1 - s0 : 1);
    float4 bv0 = ((const float4*)b)[lane];
    float4 bv1 = ((const float4*)b)[lane + 32];
    float4 z = make_float4(0.f, 0.f, 0.f, 0.f);
    float4 c0v = b2 ? ((const float4*)b2)[lane]      : z;
    float4 c1v = b2 ? ((const float4*)b2)[lane + 32] : z;
    float4 ad0 = ((const float4*)g_h)[(size_t)i * 64 + lane];
    float4 ad1 = ((const float4*)g_h)[(size_t)i * 64 + lane + 32];
    float4 r0, r1;
    r0.x = fmaxf(acc0.x * inv + bv0.x + c0v.x + ad0.x, 0.f);
    r0.y = fmaxf(acc0.y * inv + bv0.y + c0v.y + ad0.y, 0.f);
    r0.z = fmaxf(acc0.z * inv + bv0.z + c0v.z + ad0.z, 0.f);
    r0.w = fmaxf(acc0.w * inv + bv0.w + c0v.w + ad0.w, 0.f);
    r1.x = fmaxf(acc1.x * inv + bv1.x + c1v.x + ad1.x, 0.f);
    r1.y = fmaxf(acc1.y * inv + bv1.y + c1v.y + ad1.y, 0.f);
    r1.z = fmaxf(acc1.z * inv + bv1.z + c1v.z + ad1.z, 0.f);
    r1.w = fmaxf(acc1.w * inv + bv1.w + c1v.w + ad1.w, 0.f);
    float4* out = out_sel ? (float4*)out_ext : (float4*)g_h;
    out[(size_t)i * 64 + lane]      = r0;
    out[(size_t)i * 64 + lane + 32] = r1;
}

// -------------------------------------------------- edge_index passthrough
__global__ void k_copy_edges_f32(const int* __restrict__ ei,
                                 float* __restrict__ out, int n) {
    int t = blockIdx.x * blockDim.x + threadIdx.x;
    if (t < n) out[t] = (float)ei[t];
}
__global__ void k_copy_edges_raw(const int* __restrict__ ei,
                                 int* __restrict__ out, int n) {
    int t = blockIdx.x * blockDim.x + threadIdx.x;
    if (t < n) out[t] = ei[t];
}

// ---------------------------------------------------------------- launcher
extern "C" void kernel_launch(void* const* d_in, const int* in_sizes, int n_in,
                              void* d_out, int out_size) {
    const float* x      = (const float*)d_in[0];
    const int*   ei     = (const int*)d_in[1];     // int32! (JAX x64 disabled)
    const float* W0     = (const float*)d_in[2];
    const float* u0     = (const float*)d_in[3];
    const float* c0     = (const float*)d_in[4];
    const float* b0     = (const float*)d_in[5];
    const float* skipW0 = (const float*)d_in[6];
    const float* skipb0 = (const float*)d_in[7];
    const float* W1     = (const float*)d_in[8];
    const float* u1     = (const float*)d_in[9];
    const float* c1     = (const float*)d_in[10];
    const float* b1     = (const float*)d_in[11];

    int N = in_sizes[0] / 128;   // nodes
    int E = in_sizes[1] / 2;     // edges
    if (N > MAXN || E > MAXE) return;

    float* out = (float*)d_out;

    // 1) CSR build
    k_init<<<(N + 255) / 256, 256>>>(N);
    k_hist<<<(E + 255) / 256, 256>>>(ei, E, N);
    k_scan<<<1, 1024>>>(N);
    k_fill<<<(E + N + 255) / 256, 256>>>(ei, E, N);

    // 2) conv0 attention projections (from x)
    k_nodep<<<(N * 32 + 255) / 256, 256>>>(x, 0, u0, c0, 128, N);

    // 3) g_y = x @ W0   [N,1024]
    {
        dim3 grid(1024 / 128, (N + 127) / 128);
        k_sgemm<<<grid, 256>>>(x, 0, W0, 0, N, 1024, 128);
    }
    // 4) g_h = x @ skipW0   [N,256]
    {
        dim3 grid(256 / 128, (N + 127) / 128);
        k_sgemm<<<grid, 256>>>(x, 0, skipW0, 1, N, 256, 128);
    }
    // 5) aggregate0: g_h = relu(mean + b0 + g_h + skipb0)
    k_aggregate<<<(N * 32 + 255) / 256, 256>>>(b0, skipb0, (float*)nullptr, 0, N);

    // 6) conv1 attention projections (from g_h)
    k_nodep<<<(N * 32 + 255) / 256, 256>>>((const float*)nullptr, 1, u1, c1, 256, N);

    // 7) g_y = g_h @ W1   [N,1024]
    {
        dim3 grid(1024 / 128, (N + 127) / 128);
        k_sgemm<<<grid, 256>>>((const float*)nullptr, 1, W1, 0, N, 1024, 256);
    }
    // 8) aggregate1: out = relu(mean + b1 + g_h)
    k_aggregate<<<(N * 32 + 255) / 256, 256>>>(b1, (const float*)nullptr, out, 1, N);

    // 9) edge_index passthrough: 2E int32 values appended after N*256 floats
    long long hElems = (long long)N * 256;
    long long rem = (long long)out_size - hElems;
    if (rem >= 2LL * E) {
        // values cast to the fp32 output dtype (exact for idx < 2^24)
        k_copy_edges_f32<<<(2 * E + 255) / 256, 256>>>(ei, out + hElems, 2 * E);
    }
}

// round 4
// speedup vs baseline: 1.2124x; 1.2124x over previous
#include <cuda_runtime.h>
#include <cstdint>

// ---------------------------------------------------------------------------
// FeaStEncoderBlock: two FeaStConv(H=4) residual blocks.
// GEMMs now run on tensor cores: mma.sync m16n8k8 tf32 with 2-term split
// (hi+lo), giving fp32-grade accuracy at tensor-core speed.
// ---------------------------------------------------------------------------

#define MAXN 20000
#define MAXE 320000

__device__ __align__(16) float g_y[(size_t)MAXN * 1024];   // 82 MB
__device__ __align__(16) float g_h[(size_t)MAXN * 256];    // 20 MB
__device__ __align__(16) float g_ea[MAXN * 4];
__device__ __align__(16) float g_eb[MAXN * 4];
__device__ int   g_deg[MAXN];
__device__ int   g_cur[MAXN];
__device__ int   g_offs[MAXN + 1];
__device__ int   g_srcs[MAXN + MAXE];

// ---------------------------------------------------------------- CSR build
__global__ void k_init(int n) {
    int i = blockIdx.x * blockDim.x + threadIdx.x;
    if (i < n) { g_deg[i] = 1; g_cur[i] = 0; }
}

__global__ void k_hist(const int* __restrict__ ei, int E, int n) {
    int t = blockIdx.x * blockDim.x + threadIdx.x;
    if (t < E) {
        int d = ei[E + t];
        if (d >= 0 && d < n) atomicAdd(&g_deg[d], 1);
    }
}

__global__ void k_scan(int n) {
    __shared__ int sh[1024];
    __shared__ int carry;
    if (threadIdx.x == 0) carry = 0;
    __syncthreads();
    int nchunks = (n + 1023) / 1024;
    for (int chunk = 0; chunk < nchunks; ++chunk) {
        int i = chunk * 1024 + threadIdx.x;
        int v = (i < n) ? g_deg[i] : 0;
        sh[threadIdx.x] = v;
        __syncthreads();
        #pragma unroll
        for (int off = 1; off < 1024; off <<= 1) {
            int t = (threadIdx.x >= off) ? sh[threadIdx.x - off] : 0;
            __syncthreads();
            sh[threadIdx.x] += t;
            __syncthreads();
        }
        int incl = sh[threadIdx.x] + carry;
        if (i < n) g_offs[i + 1] = incl;
        __syncthreads();
        if (threadIdx.x == 1023) carry = incl;
        __syncthreads();
    }
    if (threadIdx.x == 0) g_offs[0] = 0;
}

__global__ void k_fill(const int* __restrict__ ei, int E, int n) {
    int t = blockIdx.x * blockDim.x + threadIdx.x;
    if (t >= E + n) return;
    int s, d;
    if (t < E) { s = ei[t]; d = ei[E + t]; }
    else       { s = d = t - E; }
    if (s < 0 || s >= n || d < 0 || d >= n) return;
    int pos = g_offs[d] + atomicAdd(&g_cur[d], 1);
    g_srcs[pos] = s;
}

// -------------------------------------------- per-node attention projections
__global__ void k_nodep(const float* __restrict__ x_ext, int x_sel,
                        const float* __restrict__ u,
                        const float* __restrict__ c, int K, int n) {
    int warp = (blockIdx.x * blockDim.x + threadIdx.x) >> 5;
    int lane = threadIdx.x & 31;
    if (warp >= n) return;
    const float* x = x_sel ? g_h : x_ext;
    const float* xr = x + (size_t)warp * K;
    float a0 = 0.f, a1 = 0.f, a2 = 0.f, a3 = 0.f;
    for (int k = lane; k < K; k += 32) {
        float xv = xr[k];
        float4 uv = ((const float4*)u)[k];
        a0 += xv * uv.x; a1 += xv * uv.y; a2 += xv * uv.z; a3 += xv * uv.w;
    }
    #pragma unroll
    for (int off = 16; off; off >>= 1) {
        a0 += __shfl_down_sync(0xffffffffu, a0, off);
        a1 += __shfl_down_sync(0xffffffffu, a1, off);
        a2 += __shfl_down_sync(0xffffffffu, a2, off);
        a3 += __shfl_down_sync(0xffffffffu, a3, off);
    }
    if (lane == 0) {
        float4 ea, eb;
        ea.x = expf(a0 + c[0]); ea.y = expf(a1 + c[1]);
        ea.z = expf(a2 + c[2]); ea.w = expf(a3 + c[3]);
        eb.x = expf(-a0); eb.y = expf(-a1); eb.z = expf(-a2); eb.w = expf(-a3);
        ((float4*)g_ea)[warp] = ea;
        ((float4*)g_eb)[warp] = eb;
    }
}

// --------------------------------------------------------- tf32 MMA GEMM
__device__ __forceinline__ unsigned f2tf32(float x) {
    unsigned r;
    asm("cvt.rna.tf32.f32 %0, %1;" : "=r"(r) : "f"(x));
    return r;
}
__device__ __forceinline__ void split_tf32(float x, unsigned& hi, unsigned& lo) {
    hi = f2tf32(x);
    lo = f2tf32(x - __uint_as_float(hi));
}
__device__ __forceinline__ void mma_tf32(float* c, const unsigned* a, const unsigned* b) {
    asm volatile(
        "mma.sync.aligned.m16n8k8.row.col.f32.tf32.tf32.f32 "
        "{%0,%1,%2,%3}, {%4,%5,%6,%7}, {%8,%9}, {%0,%1,%2,%3};"
        : "+f"(c[0]), "+f"(c[1]), "+f"(c[2]), "+f"(c[3])
        : "r"(a[0]), "r"(a[1]), "r"(a[2]), "r"(a[3]), "r"(b[0]), "r"(b[1]));
}

// C[M,N] = A[M,K] @ B[K,N], row-major. 128x128 block, BK=32.
// 8 warps: 2(m) x 4(n), each warp 64x32 = 4x4 m16n8k8 tiles.
// 2-term tf32 split: 3 MMAs per tile (hi*hi + hi*lo + lo*hi).
#define SA 36    // As row stride [m][k]
#define SB 136   // Bs row stride [k][n]
__global__ void __launch_bounds__(256) k_mma(const float* __restrict__ A_ext,
                                             int a_sel,
                                             const float* __restrict__ B,
                                             int c_sel,
                                             int M, int N, int K) {
    __shared__ float As[128 * SA];
    __shared__ float Bs[32 * SB];
    const float* A = a_sel ? g_h : A_ext;
    float* C = c_sel ? g_h : g_y;

    int tid = threadIdx.x;
    int wid = tid >> 5, lane = tid & 31;
    int g   = lane >> 2;        // group id 0..7
    int tig = lane & 3;         // thread-in-group 0..3
    int wm = (wid >> 2) * 64;   // warp m offset within block: 0 or 64
    int wn = (wid & 3) * 32;    // warp n offset: 0,32,64,96
    int m0 = blockIdx.y * 128;
    int n0 = blockIdx.x * 128;

    float acc[4][4][4];
    #pragma unroll
    for (int i = 0; i < 4; i++)
        #pragma unroll
        for (int j = 0; j < 4; j++) {
            acc[i][j][0] = 0.f; acc[i][j][1] = 0.f;
            acc[i][j][2] = 0.f; acc[i][j][3] = 0.f;
        }

    // A tile load mapping: thread t -> row t/2, 16 floats at k=(t%2)*16
    int am = tid >> 1;
    int ak = (tid & 1) * 16;
    bool a_ok = (m0 + am) < M;
    // B tile load mapping: thread t -> k = t/32 (+8*i), n = (t%32)*4
    int bk = tid >> 5;
    int bn = (tid & 31) * 4;

    for (int k0 = 0; k0 < K; k0 += 32) {
        const float* Ap = A + (size_t)(m0 + am) * K + k0 + ak;
        #pragma unroll
        for (int i = 0; i < 4; i++) {
            float4 v = a_ok ? *(const float4*)(Ap + 4 * i)
                            : make_float4(0.f, 0.f, 0.f, 0.f);
            *(float4*)&As[am * SA + ak + 4 * i] = v;
        }
        #pragma unroll
        for (int i = 0; i < 4; i++) {
            float4 v = *(const float4*)(B + (size_t)(k0 + bk + 8 * i) * N + n0 + bn);
            *(float4*)&Bs[(bk + 8 * i) * SB + bn] = v;
        }
        __syncthreads();

        #pragma unroll
        for (int kk = 0; kk < 32; kk += 8) {
            unsigned ah[4][4], al[4][4];
            #pragma unroll
            for (int mt = 0; mt < 4; mt++) {
                int mr = wm + mt * 16 + g;
                float v0 = As[(mr)     * SA + kk + tig];
                float v1 = As[(mr + 8) * SA + kk + tig];
                float v2 = As[(mr)     * SA + kk + 4 + tig];
                float v3 = As[(mr + 8) * SA + kk + 4 + tig];
                split_tf32(v0, ah[mt][0], al[mt][0]);
                split_tf32(v1, ah[mt][1], al[mt][1]);
                split_tf32(v2, ah[mt][2], al[mt][2]);
                split_tf32(v3, ah[mt][3], al[mt][3]);
            }
            unsigned bh[4][2], bl[4][2];
            #pragma unroll
            for (int nt = 0; nt < 4; nt++) {
                int nc = wn + nt * 8 + g;
                float v0 = Bs[(kk + tig)     * SB + nc];
                float v1 = Bs[(kk + 4 + tig) * SB + nc];
                split_tf32(v0, bh[nt][0], bl[nt][0]);
                split_tf32(v1, bh[nt][1], bl[nt][1]);
            }
            #pragma unroll
            for (int mt = 0; mt < 4; mt++)
                #pragma unroll
                for (int nt = 0; nt < 4; nt++) {
                    mma_tf32(acc[mt][nt], ah[mt], bl[nt]);
                    mma_tf32(acc[mt][nt], al[mt], bh[nt]);
                    mma_tf32(acc[mt][nt], ah[mt], bh[nt]);
                }
        }
        __syncthreads();
    }

    #pragma unroll
    for (int mt = 0; mt < 4; mt++) {
        int r = m0 + wm + mt * 16 + g;
        #pragma unroll
        for (int nt = 0; nt < 4; nt++) {
            int cc = n0 + wn + nt * 8 + tig * 2;
            if (r < M) {
                C[(size_t)r * N + cc]     = acc[mt][nt][0];
                C[(size_t)r * N + cc + 1] = acc[mt][nt][1];
            }
            if (r + 8 < M) {
                C[(size_t)(r + 8) * N + cc]     = acc[mt][nt][2];
                C[(size_t)(r + 8) * N + cc + 1] = acc[mt][nt][3];
            }
        }
    }
}

// --------------------------------------------------------------- aggregate
__device__ __forceinline__ float4 fma4(float4 a, float s, float4 v) {
    a.x += s * v.x; a.y += s * v.y; a.z += s * v.z; a.w += s * v.w; return a;
}

__global__ void k_aggregate(const float* __restrict__ b,
                            const float* __restrict__ b2,
                            float* __restrict__ out_ext, int out_sel,
                            int n) {
    int warp = (blockIdx.x * blockDim.x + threadIdx.x) >> 5;
    int lane = threadIdx.x & 31;
    if (warp >= n) return;
    int i  = warp;
    int s0 = g_offs[i], s1 = g_offs[i + 1];
    float4 ebi = ((const float4*)g_eb)[i];
    float4 acc0 = make_float4(0.f, 0.f, 0.f, 0.f);
    float4 acc1 = make_float4(0.f, 0.f, 0.f, 0.f);

    for (int e = s0; e < s1; ++e) {
        int j = g_srcs[e];
        float4 a = ((const float4*)g_ea)[j];
        float q0 = a.x * ebi.x, q1 = a.y * ebi.y, q2 = a.z * ebi.z, q3 = a.w * ebi.w;
        float rz = 1.0f / (q0 + q1 + q2 + q3);
        q0 *= rz; q1 *= rz; q2 *= rz; q3 *= rz;
        const float4* yj = (const float4*)(g_y + (size_t)j * 1024);
        acc0 = fma4(acc0, q0, yj[0 * 64 + lane]);
        acc1 = fma4(acc1, q0, yj[0 * 64 + lane + 32]);
        acc0 = fma4(acc0, q1, yj[1 * 64 + lane]);
        acc1 = fma4(acc1, q1, yj[1 * 64 + lane + 32]);
        acc0 = fma4(acc0, q2, yj[2 * 64 + lane]);
        acc1 = fma4(acc1, q2, yj[2 * 64 + lane + 32]);
        acc0 = fma4(acc0, q3, yj[3 * 64 + lane]);
        acc1 = fma4(acc1, q3, yj[3 * 64 + lane + 32]);
    }
    float inv = 1.0f / (float)(s1 - s0 > 0 ? s1 - s0 : 1);
    float4 bv0 = ((const float4*)b)[lane];
    float4 bv1 = ((const float4*)b)[lane + 32];
    float4 z = make_float4(0.f, 0.f, 0.f, 0.f);
    float4 c0v = b2 ? ((const float4*)b2)[lane]      : z;
    float4 c1v = b2 ? ((const float4*)b2)[lane + 32] : z;
    float4 ad0 = ((const float4*)g_h)[(size_t)i * 64 + lane];
    float4 ad1 = ((const float4*)g_h)[(size_t)i * 64 + lane + 32];
    float4 r0, r1;
    r0.x = fmaxf(acc0.x * inv + bv0.x + c0v.x + ad0.x, 0.f);
    r0.y = fmaxf(acc0.y * inv + bv0.y + c0v.y + ad0.y, 0.f);
    r0.z = fmaxf(acc0.z * inv + bv0.z + c0v.z + ad0.z, 0.f);
    r0.w = fmaxf(acc0.w * inv + bv0.w + c0v.w + ad0.w, 0.f);
    r1.x = fmaxf(acc1.x * inv + bv1.x + c1v.x + ad1.x, 0.f);
    r1.y = fmaxf(acc1.y * inv + bv1.y + c1v.y + ad1.y, 0.f);
    r1.z = fmaxf(acc1.z * inv + bv1.z + c1v.z + ad1.z, 0.f);
    r1.w = fmaxf(acc1.w * inv + bv1.w + c1v.w + ad1.w, 0.f);
    float4* out = out_sel ? (float4*)out_ext : (float4*)g_h;
    out[(size_t)i * 64 + lane]      = r0;
    out[(size_t)i * 64 + lane + 32] = r1;
}

// -------------------------------------------------- edge_index passthrough
__global__ void k_copy_edges_f32(const int* __restrict__ ei,
                                 float* __restrict__ out, int n) {
    int t = blockIdx.x * blockDim.x + threadIdx.x;
    if (t < n) out[t] = (float)ei[t];
}

// ---------------------------------------------------------------- launcher
extern "C" void kernel_launch(void* const* d_in, const int* in_sizes, int n_in,
                              void* d_out, int out_size) {
    const float* x      = (const float*)d_in[0];
    const int*   ei     = (const int*)d_in[1];     // int32 (JAX x64 disabled)
    const float* W0     = (const float*)d_in[2];
    const float* u0     = (const float*)d_in[3];
    const float* c0     = (const float*)d_in[4];
    const float* b0     = (const float*)d_in[5];
    const float* skipW0 = (const float*)d_in[6];
    const float* skipb0 = (const float*)d_in[7];
    const float* W1     = (const float*)d_in[8];
    const float* u1     = (const float*)d_in[9];
    const float* c1     = (const float*)d_in[10];
    const float* b1     = (const float*)d_in[11];

    int N = in_sizes[0] / 128;
    int E = in_sizes[1] / 2;
    if (N > MAXN || E > MAXE) return;

    float* out = (float*)d_out;

    // 1) CSR build
    k_init<<<(N + 255) / 256, 256>>>(N);
    k_hist<<<(E + 255) / 256, 256>>>(ei, E, N);
    k_scan<<<1, 1024>>>(N);
    k_fill<<<(E + N + 255) / 256, 256>>>(ei, E, N);

    // 2) conv0 attention projections (from x)
    k_nodep<<<(N * 32 + 255) / 256, 256>>>(x, 0, u0, c0, 128, N);

    // 3) g_y = x @ W0   [N,1024]  (tensor cores)
    {
        dim3 grid(1024 / 128, (N + 127) / 128);
        k_mma<<<grid, 256>>>(x, 0, W0, 0, N, 1024, 128);
    }
    // 4) g_h = x @ skipW0   [N,256]
    {
        dim3 grid(256 / 128, (N + 127) / 128);
        k_mma<<<grid, 256>>>(x, 0, skipW0, 1, N, 256, 128);
    }
    // 5) aggregate0: g_h = relu(mean + b0 + g_h + skipb0)
    k_aggregate<<<(N * 32 + 255) / 256, 256>>>(b0, skipb0, (float*)nullptr, 0, N);

    // 6) conv1 attention projections (from g_h)
    k_nodep<<<(N * 32 + 255) / 256, 256>>>((const float*)nullptr, 1, u1, c1, 256, N);

    // 7) g_y = g_h @ W1   [N,1024]
    {
        dim3 grid(1024 / 128, (N + 127) / 128);
        k_mma<<<grid, 256>>>((const float*)nullptr, 1, W1, 0, N, 1024, 256);
    }
    // 8) aggregate1: out = relu(mean + b1 + g_h)
    k_aggregate<<<(N * 32 + 255) / 256, 256>>>(b1, (const float*)nullptr, out, 1, N);

    // 9) edge_index passthrough
    long long hElems = (long long)N * 256;
    long long rem = (long long)out_size - hElems;
    if (rem >= 2LL * E) {
        k_copy_edges_f32<<<(2 * E + 255) / 256, 256>>>(ei, out + hElems, 2 * E);
    }
}

// round 5
// speedup vs baseline: 1.2367x; 1.0200x over previous
#include <cuda_runtime.h>
#include <cstdint>

// ---------------------------------------------------------------------------
// FeaStEncoderBlock, input-space aggregation formulation:
//   out_i = relu( sum_h (mean_j q_hij x_j) @ W_h  + bias + skip )
// Per conv:
//   1. nodep: p = x@u -> ea=exp(p+c), eb=exp(-p)  (softmax factorization)
//   2. agg_in: z[i, h*in + c] = (1/deg) sum_j q_hij x[j,c]   (+ x_i tail for skip)
//   3. wstack: Wstack[h*in+c, d] = W[c, h*out+d]  (+ skipW rows)
//   4. mma: out = relu(z @ Wstack + b (+b2) (+addend))   -- tf32 3-split, fused epilogue
// ---------------------------------------------------------------------------

#define MAXN 20000
#define MAXE 320000

__device__ __align__(16) float g_y[(size_t)MAXN * 1024];   // z buffer
__device__ __align__(16) float g_h[(size_t)MAXN * 256];    // hidden h
__device__ __align__(16) float g_wb[1024 * 256];           // stacked weights
__device__ __align__(16) float g_ea[MAXN * 4];
__device__ __align__(16) float g_eb[MAXN * 4];
__device__ int   g_deg[MAXN];
__device__ int   g_cur[MAXN];
__device__ int   g_offs[MAXN + 1];
__device__ int   g_srcs[MAXN + MAXE];

// ---------------------------------------------------------------- CSR build
__global__ void k_init(int n) {
    int i = blockIdx.x * blockDim.x + threadIdx.x;
    if (i < n) { g_deg[i] = 1; g_cur[i] = 0; }
}

__global__ void k_hist(const int* __restrict__ ei, int E, int n) {
    int t = blockIdx.x * blockDim.x + threadIdx.x;
    if (t < E) {
        int d = ei[E + t];
        if (d >= 0 && d < n) atomicAdd(&g_deg[d], 1);
    }
}

__global__ void k_scan(int n) {
    __shared__ int sh[1024];
    __shared__ int carry;
    if (threadIdx.x == 0) carry = 0;
    __syncthreads();
    int nchunks = (n + 1023) / 1024;
    for (int chunk = 0; chunk < nchunks; ++chunk) {
        int i = chunk * 1024 + threadIdx.x;
        int v = (i < n) ? g_deg[i] : 0;
        sh[threadIdx.x] = v;
        __syncthreads();
        #pragma unroll
        for (int off = 1; off < 1024; off <<= 1) {
            int t = (threadIdx.x >= off) ? sh[threadIdx.x - off] : 0;
            __syncthreads();
            sh[threadIdx.x] += t;
            __syncthreads();
        }
        int incl = sh[threadIdx.x] + carry;
        if (i < n) g_offs[i + 1] = incl;
        __syncthreads();
        if (threadIdx.x == 1023) carry = incl;
        __syncthreads();
    }
    if (threadIdx.x == 0) g_offs[0] = 0;
}

__global__ void k_fill(const int* __restrict__ ei, int E, int n) {
    int t = blockIdx.x * blockDim.x + threadIdx.x;
    if (t >= E + n) return;
    int s, d;
    if (t < E) { s = ei[t]; d = ei[E + t]; }
    else       { s = d = t - E; }
    if (s < 0 || s >= n || d < 0 || d >= n) return;
    int pos = g_offs[d] + atomicAdd(&g_cur[d], 1);
    g_srcs[pos] = s;
}

// -------------------------------------------- per-node attention projections
__global__ void k_nodep(const float* __restrict__ x_ext, int x_sel,
                        const float* __restrict__ u,
                        const float* __restrict__ c, int K, int n) {
    int warp = (blockIdx.x * blockDim.x + threadIdx.x) >> 5;
    int lane = threadIdx.x & 31;
    if (warp >= n) return;
    const float* x = x_sel ? g_h : x_ext;
    const float* xr = x + (size_t)warp * K;
    float a0 = 0.f, a1 = 0.f, a2 = 0.f, a3 = 0.f;
    for (int k = lane; k < K; k += 32) {
        float xv = xr[k];
        float4 uv = ((const float4*)u)[k];
        a0 += xv * uv.x; a1 += xv * uv.y; a2 += xv * uv.z; a3 += xv * uv.w;
    }
    #pragma unroll
    for (int off = 16; off; off >>= 1) {
        a0 += __shfl_down_sync(0xffffffffu, a0, off);
        a1 += __shfl_down_sync(0xffffffffu, a1, off);
        a2 += __shfl_down_sync(0xffffffffu, a2, off);
        a3 += __shfl_down_sync(0xffffffffu, a3, off);
    }
    if (lane == 0) {
        float4 ea, eb;
        ea.x = expf(a0 + c[0]); ea.y = expf(a1 + c[1]);
        ea.z = expf(a2 + c[2]); ea.w = expf(a3 + c[3]);
        eb.x = expf(-a0); eb.y = expf(-a1); eb.z = expf(-a2); eb.w = expf(-a3);
        ((float4*)g_ea)[warp] = ea;
        ((float4*)g_eb)[warp] = eb;
    }
}

// ------------------------------------------------ input-space aggregation
// One warp per node i. acc[h][:] += q_h(j,i) * x[j,:]; z[i,h*IN+c] = acc/deg.
// If ZC > 4*IN, also copy x_i into cols [4*IN, 4*IN+IN) (skip-concat).
__device__ __forceinline__ float4 fma4(float4 a, float s, float4 v) {
    a.x += s * v.x; a.y += s * v.y; a.z += s * v.z; a.w += s * v.w; return a;
}

template<int IN, int ZC>
__global__ void k_agg_in(const float* __restrict__ x_ext, int x_sel, int n) {
    constexpr int V = IN / 128;          // float4 chunks per lane (1 or 2)
    int warp = (blockIdx.x * blockDim.x + threadIdx.x) >> 5;
    int lane = threadIdx.x & 31;
    if (warp >= n) return;
    const float* x = x_sel ? g_h : x_ext;
    int i  = warp;
    int s0 = g_offs[i], s1 = g_offs[i + 1];
    float4 ebi = ((const float4*)g_eb)[i];

    float4 acc[4][V];
    #pragma unroll
    for (int h = 0; h < 4; h++)
        #pragma unroll
        for (int v = 0; v < V; v++) acc[h][v] = make_float4(0.f, 0.f, 0.f, 0.f);

    for (int e = s0; e < s1; ++e) {
        int j = g_srcs[e];
        float4 a = ((const float4*)g_ea)[j];
        float q0 = a.x * ebi.x, q1 = a.y * ebi.y, q2 = a.z * ebi.z, q3 = a.w * ebi.w;
        float rz = 1.0f / (q0 + q1 + q2 + q3);
        q0 *= rz; q1 *= rz; q2 *= rz; q3 *= rz;
        const float4* xj = (const float4*)(x + (size_t)j * IN);
        #pragma unroll
        for (int v = 0; v < V; v++) {
            float4 xv = xj[lane + 32 * v];
            acc[0][v] = fma4(acc[0][v], q0, xv);
            acc[1][v] = fma4(acc[1][v], q1, xv);
            acc[2][v] = fma4(acc[2][v], q2, xv);
            acc[3][v] = fma4(acc[3][v], q3, xv);
        }
    }
    float inv = 1.0f / (float)(s1 - s0 > 0 ? s1 - s0 : 1);
    float4* z = (float4*)(g_y + (size_t)i * ZC);
    #pragma unroll
    for (int h = 0; h < 4; h++)
        #pragma unroll
        for (int v = 0; v < V; v++) {
            float4 r = acc[h][v];
            r.x *= inv; r.y *= inv; r.z *= inv; r.w *= inv;
            z[h * (IN / 4) + lane + 32 * v] = r;
        }
    if (ZC > 4 * IN) {
        const float4* xi = (const float4*)(x + (size_t)i * IN);
        #pragma unroll
        for (int v = 0; v < V; v++)
            z[IN + lane + 32 * v] = xi[lane + 32 * v];   // 4*IN/4 == IN
    }
}

// ------------------------------------------------- stacked weight builders
// Wstack[h*in + c, d] = W[c, h*out + d]; optional skip rows appended.
__global__ void k_wstack0(const float* __restrict__ W0,
                          const float* __restrict__ skipW0) {
    int t = blockIdx.x * blockDim.x + threadIdx.x;
    if (t >= 640 * 256) return;
    int rr = t >> 8, d = t & 255;
    float v;
    if (rr < 512) { int h = rr >> 7, c = rr & 127; v = W0[c * 1024 + h * 256 + d]; }
    else          { int c = rr - 512;              v = skipW0[c * 256 + d]; }
    g_wb[t] = v;
}
__global__ void k_wstack1(const float* __restrict__ W1) {
    int t = blockIdx.x * blockDim.x + threadIdx.x;
    if (t >= 1024 * 256) return;
    int rr = t >> 8, d = t & 255;
    int h = rr >> 8, c = rr & 255;
    g_wb[t] = W1[c * 1024 + h * 256 + d];
}

// --------------------------------------------------------- tf32 MMA GEMM
__device__ __forceinline__ unsigned f2tf32(float x) {
    unsigned r;
    asm("cvt.rna.tf32.f32 %0, %1;" : "=r"(r) : "f"(x));
    return r;
}
__device__ __forceinline__ void split_tf32(float x, unsigned& hi, unsigned& lo) {
    hi = f2tf32(x);
    lo = f2tf32(x - __uint_as_float(hi));
}
__device__ __forceinline__ void mma_tf32(float* c, const unsigned* a, const unsigned* b) {
    asm volatile(
        "mma.sync.aligned.m16n8k8.row.col.f32.tf32.tf32.f32 "
        "{%0,%1,%2,%3}, {%4,%5,%6,%7}, {%8,%9}, {%0,%1,%2,%3};"
        : "+f"(c[0]), "+f"(c[1]), "+f"(c[2]), "+f"(c[3])
        : "r"(a[0]), "r"(a[1]), "r"(a[2]), "r"(a[3]), "r"(b[0]), "r"(b[1]));
}

// C = relu(A@B + b (+b2) (+addend)).  A: g_y [M,K]. B: g_wb [K,256].
// out_sel: 0 -> g_h, 1 -> out_ext.  add_sel: 1 -> += g_h row.
#define SA 36
#define SB 136
__global__ void __launch_bounds__(256) k_mma(const float* __restrict__ b,
                                             const float* __restrict__ b2,
                                             int add_sel,
                                             float* __restrict__ out_ext, int out_sel,
                                             int M, int N, int K) {
    __shared__ float As[128 * SA];
    __shared__ float Bs[32 * SB];
    const float* A = g_y;
    const float* B = g_wb;
    float* C = out_sel ? out_ext : g_h;

    int tid = threadIdx.x;
    int wid = tid >> 5, lane = tid & 31;
    int g   = lane >> 2;
    int tig = lane & 3;
    int wm = (wid >> 2) * 64;
    int wn = (wid & 3) * 32;
    int m0 = blockIdx.y * 128;
    int n0 = blockIdx.x * 128;

    float acc[4][4][4];
    #pragma unroll
    for (int i = 0; i < 4; i++)
        #pragma unroll
        for (int j = 0; j < 4; j++) {
            acc[i][j][0] = 0.f; acc[i][j][1] = 0.f;
            acc[i][j][2] = 0.f; acc[i][j][3] = 0.f;
        }

    int am = tid >> 1;
    int ak = (tid & 1) * 16;
    bool a_ok = (m0 + am) < M;
    int bk = tid >> 5;
    int bn = (tid & 31) * 4;

    for (int k0 = 0; k0 < K; k0 += 32) {
        const float* Ap = A + (size_t)(m0 + am) * K + k0 + ak;
        #pragma unroll
        for (int i = 0; i < 4; i++) {
            float4 v = a_ok ? *(const float4*)(Ap + 4 * i)
                            : make_float4(0.f, 0.f, 0.f, 0.f);
            *(float4*)&As[am * SA + ak + 4 * i] = v;
        }
        #pragma unroll
        for (int i = 0; i < 4; i++) {
            float4 v = *(const float4*)(B + (size_t)(k0 + bk + 8 * i) * N + n0 + bn);
            *(float4*)&Bs[(bk + 8 * i) * SB + bn] = v;
        }
        __syncthreads();

        #pragma unroll
        for (int kk = 0; kk < 32; kk += 8) {
            unsigned ah[4][4], al[4][4];
            #pragma unroll
            for (int mt = 0; mt < 4; mt++) {
                int mr = wm + mt * 16 + g;
                float v0 = As[(mr)     * SA + kk + tig];
                float v1 = As[(mr + 8) * SA + kk + tig];
                float v2 = As[(mr)     * SA + kk + 4 + tig];
                float v3 = As[(mr + 8) * SA + kk + 4 + tig];
                split_tf32(v0, ah[mt][0], al[mt][0]);
                split_tf32(v1, ah[mt][1], al[mt][1]);
                split_tf32(v2, ah[mt][2], al[mt][2]);
                split_tf32(v3, ah[mt][3], al[mt][3]);
            }
            unsigned bh[4][2], bl[4][2];
            #pragma unroll
            for (int nt = 0; nt < 4; nt++) {
                int nc = wn + nt * 8 + g;
                float v0 = Bs[(kk + tig)     * SB + nc];
                float v1 = Bs[(kk + 4 + tig) * SB + nc];
                split_tf32(v0, bh[nt][0], bl[nt][0]);
                split_tf32(v1, bh[nt][1], bl[nt][1]);
            }
            #pragma unroll
            for (int mt = 0; mt < 4; mt++)
                #pragma unroll
                for (int nt = 0; nt < 4; nt++) {
                    mma_tf32(acc[mt][nt], ah[mt], bl[nt]);
                    mma_tf32(acc[mt][nt], al[mt], bh[nt]);
                    mma_tf32(acc[mt][nt], ah[mt], bh[nt]);
                }
        }
        __syncthreads();
    }

    // ---- fused epilogue: bias (+bias2) (+residual) + relu ----
    #pragma unroll
    for (int mt = 0; mt < 4; mt++) {
        int r = m0 + wm + mt * 16 + g;
        #pragma unroll
        for (int nt = 0; nt < 4; nt++) {
            int cc = n0 + wn + nt * 8 + tig * 2;
            float bb0 = b[cc], bb1 = b[cc + 1];
            if (b2) { bb0 += b2[cc]; bb1 += b2[cc + 1]; }
            if (r < M) {
                float v0 = acc[mt][nt][0] + bb0;
                float v1 = acc[mt][nt][1] + bb1;
                if (add_sel) {
                    v0 += g_h[(size_t)r * 256 + cc];
                    v1 += g_h[(size_t)r * 256 + cc + 1];
                }
                C[(size_t)r * N + cc]     = fmaxf(v0, 0.f);
                C[(size_t)r * N + cc + 1] = fmaxf(v1, 0.f);
            }
            if (r + 8 < M) {
                float v2 = acc[mt][nt][2] + bb0;
                float v3 = acc[mt][nt][3] + bb1;
                if (add_sel) {
                    v2 += g_h[(size_t)(r + 8) * 256 + cc];
                    v3 += g_h[(size_t)(r + 8) * 256 + cc + 1];
                }
                C[(size_t)(r + 8) * N + cc]     = fmaxf(v2, 0.f);
                C[(size_t)(r + 8) * N + cc + 1] = fmaxf(v3, 0.f);
            }
        }
    }
}

// -------------------------------------------------- edge_index passthrough
__global__ void k_copy_edges_f32(const int* __restrict__ ei,
                                 float* __restrict__ out, int n) {
    int t = blockIdx.x * blockDim.x + threadIdx.x;
    if (t < n) out[t] = (float)ei[t];
}

// ---------------------------------------------------------------- launcher
extern "C" void kernel_launch(void* const* d_in, const int* in_sizes, int n_in,
                              void* d_out, int out_size) {
    const float* x      = (const float*)d_in[0];
    const int*   ei     = (const int*)d_in[1];     // int32 (JAX x64 disabled)
    const float* W0     = (const float*)d_in[2];
    const float* u0     = (const float*)d_in[3];
    const float* c0     = (const float*)d_in[4];
    const float* b0     = (const float*)d_in[5];
    const float* skipW0 = (const float*)d_in[6];
    const float* skipb0 = (const float*)d_in[7];
    const float* W1     = (const float*)d_in[8];
    const float* u1     = (const float*)d_in[9];
    const float* c1     = (const float*)d_in[10];
    const float* b1     = (const float*)d_in[11];

    int N = in_sizes[0] / 128;
    int E = in_sizes[1] / 2;
    if (N > MAXN || E > MAXE) return;

    float* out = (float*)d_out;

    // CSR build
    k_init<<<(N + 255) / 256, 256>>>(N);
    k_hist<<<(E + 255) / 256, 256>>>(ei, E, N);
    k_scan<<<1, 1024>>>(N);
    k_fill<<<(E + N + 255) / 256, 256>>>(ei, E, N);

    // ---- conv0 ----
    k_wstack0<<<(640 * 256 + 255) / 256, 256>>>(W0, skipW0);
    k_nodep<<<(N * 32 + 255) / 256, 256>>>(x, 0, u0, c0, 128, N);
    k_agg_in<128, 640><<<(N * 32 + 255) / 256, 256>>>(x, 0, N);
    {   // g_h = relu(z[:,0:640] @ Wstack0 + b0 + skipb0)
        dim3 grid(256 / 128, (N + 127) / 128);
        k_mma<<<grid, 256>>>(b0, skipb0, 0, (float*)nullptr, 0, N, 256, 640);
    }

    // ---- conv1 ----
    k_wstack1<<<(1024 * 256 + 255) / 256, 256>>>(W1);
    k_nodep<<<(N * 32 + 255) / 256, 256>>>((const float*)nullptr, 1, u1, c1, 256, N);
    k_agg_in<256, 1024><<<(N * 32 + 255) / 256, 256>>>((const float*)nullptr, 1, N);
    {   // out = relu(z @ Wstack1 + b1 + g_h)
        dim3 grid(256 / 128, (N + 127) / 128);
        k_mma<<<grid, 256>>>(b1, (const float*)nullptr, 1, out, 1, N, 256, 1024);
    }

    // edge_index passthrough
    long long hElems = (long long)N * 256;
    long long rem = (long long)out_size - hElems;
    if (rem >= 2LL * E) {
        k_copy_edges_f32<<<(2 * E + 255) / 256, 256>>>(ei, out + hElems, 2 * E);
    }
}

// round 6
// speedup vs baseline: 1.9692x; 1.5923x over previous
#include <cuda_runtime.h>
#include <cstdint>

// ---------------------------------------------------------------------------
// FeaStEncoderBlock, input-space aggregation + bf16-split tensor-core GEMM.
//   out_i = relu( sum_h (mean_j q_hij x_j) @ W_h  + bias + skip )
// GEMM: m16n8k16 bf16 mma, 2-term split (hi+lo), 3 products, split done at
// smem-store time. Tile 64x128, occupancy-3 to beat wave quantization.
// ---------------------------------------------------------------------------

#define MAXN 20000
#define MAXE 320000

__device__ __align__(16) float g_y[(size_t)MAXN * 1024];   // z buffer
__device__ __align__(16) float g_h[(size_t)MAXN * 256];    // hidden h
__device__ __align__(16) float g_wb[1024 * 256];           // stacked weights
__device__ __align__(16) float g_ea[MAXN * 4];
__device__ __align__(16) float g_eb[MAXN * 4];
__device__ int   g_deg[MAXN];
__device__ int   g_cur[MAXN];
__device__ int   g_offs[MAXN + 1];
__device__ int   g_srcs[MAXN + MAXE];

// ---------------------------------------------------------------- CSR build
__global__ void k_init(int n) {
    int i = blockIdx.x * blockDim.x + threadIdx.x;
    if (i < n) { g_deg[i] = 1; g_cur[i] = 0; }
}

__global__ void k_hist(const int* __restrict__ ei, int E, int n) {
    int t = blockIdx.x * blockDim.x + threadIdx.x;
    if (t < E) {
        int d = ei[E + t];
        if (d >= 0 && d < n) atomicAdd(&g_deg[d], 1);
    }
}

__global__ void k_scan(int n) {
    __shared__ int sh[1024];
    __shared__ int carry;
    if (threadIdx.x == 0) carry = 0;
    __syncthreads();
    int nchunks = (n + 1023) / 1024;
    for (int chunk = 0; chunk < nchunks; ++chunk) {
        int i = chunk * 1024 + threadIdx.x;
        int v = (i < n) ? g_deg[i] : 0;
        sh[threadIdx.x] = v;
        __syncthreads();
        #pragma unroll
        for (int off = 1; off < 1024; off <<= 1) {
            int t = (threadIdx.x >= off) ? sh[threadIdx.x - off] : 0;
            __syncthreads();
            sh[threadIdx.x] += t;
            __syncthreads();
        }
        int incl = sh[threadIdx.x] + carry;
        if (i < n) g_offs[i + 1] = incl;
        __syncthreads();
        if (threadIdx.x == 1023) carry = incl;
        __syncthreads();
    }
    if (threadIdx.x == 0) g_offs[0] = 0;
}

__global__ void k_fill(const int* __restrict__ ei, int E, int n) {
    int t = blockIdx.x * blockDim.x + threadIdx.x;
    if (t >= E + n) return;
    int s, d;
    if (t < E) { s = ei[t]; d = ei[E + t]; }
    else       { s = d = t - E; }
    if (s < 0 || s >= n || d < 0 || d >= n) return;
    int pos = g_offs[d] + atomicAdd(&g_cur[d], 1);
    g_srcs[pos] = s;
}

// -------------------------------------------- per-node attention projections
__global__ void k_nodep(const float* __restrict__ x_ext, int x_sel,
                        const float* __restrict__ u,
                        const float* __restrict__ c, int K, int n) {
    int warp = (blockIdx.x * blockDim.x + threadIdx.x) >> 5;
    int lane = threadIdx.x & 31;
    if (warp >= n) return;
    const float* x = x_sel ? g_h : x_ext;
    const float* xr = x + (size_t)warp * K;
    float a0 = 0.f, a1 = 0.f, a2 = 0.f, a3 = 0.f;
    for (int k = lane; k < K; k += 32) {
        float xv = xr[k];
        float4 uv = ((const float4*)u)[k];
        a0 += xv * uv.x; a1 += xv * uv.y; a2 += xv * uv.z; a3 += xv * uv.w;
    }
    #pragma unroll
    for (int off = 16; off; off >>= 1) {
        a0 += __shfl_down_sync(0xffffffffu, a0, off);
        a1 += __shfl_down_sync(0xffffffffu, a1, off);
        a2 += __shfl_down_sync(0xffffffffu, a2, off);
        a3 += __shfl_down_sync(0xffffffffu, a3, off);
    }
    if (lane == 0) {
        float4 ea, eb;
        ea.x = expf(a0 + c[0]); ea.y = expf(a1 + c[1]);
        ea.z = expf(a2 + c[2]); ea.w = expf(a3 + c[3]);
        eb.x = expf(-a0); eb.y = expf(-a1); eb.z = expf(-a2); eb.w = expf(-a3);
        ((float4*)g_ea)[warp] = ea;
        ((float4*)g_eb)[warp] = eb;
    }
}

// ------------------------------------------------ input-space aggregation
__device__ __forceinline__ float4 fma4(float4 a, float s, float4 v) {
    a.x += s * v.x; a.y += s * v.y; a.z += s * v.z; a.w += s * v.w; return a;
}

template<int IN, int ZC>
__global__ void k_agg_in(const float* __restrict__ x_ext, int x_sel, int n) {
    constexpr int V = IN / 128;
    int warp = (blockIdx.x * blockDim.x + threadIdx.x) >> 5;
    int lane = threadIdx.x & 31;
    if (warp >= n) return;
    const float* x = x_sel ? g_h : x_ext;
    int i  = warp;
    int s0 = g_offs[i], s1 = g_offs[i + 1];
    float4 ebi = ((const float4*)g_eb)[i];

    float4 acc[4][V];
    #pragma unroll
    for (int h = 0; h < 4; h++)
        #pragma unroll
        for (int v = 0; v < V; v++) acc[h][v] = make_float4(0.f, 0.f, 0.f, 0.f);

    for (int e = s0; e < s1; ++e) {
        int j = g_srcs[e];
        float4 a = ((const float4*)g_ea)[j];
        float q0 = a.x * ebi.x, q1 = a.y * ebi.y, q2 = a.z * ebi.z, q3 = a.w * ebi.w;
        float rz = 1.0f / (q0 + q1 + q2 + q3);
        q0 *= rz; q1 *= rz; q2 *= rz; q3 *= rz;
        const float4* xj = (const float4*)(x + (size_t)j * IN);
        #pragma unroll
        for (int v = 0; v < V; v++) {
            float4 xv = xj[lane + 32 * v];
            acc[0][v] = fma4(acc[0][v], q0, xv);
            acc[1][v] = fma4(acc[1][v], q1, xv);
            acc[2][v] = fma4(acc[2][v], q2, xv);
            acc[3][v] = fma4(acc[3][v], q3, xv);
        }
    }
    float inv = 1.0f / (float)(s1 - s0 > 0 ? s1 - s0 : 1);
    float4* z = (float4*)(g_y + (size_t)i * ZC);
    #pragma unroll
    for (int h = 0; h < 4; h++)
        #pragma unroll
        for (int v = 0; v < V; v++) {
            float4 r = acc[h][v];
            r.x *= inv; r.y *= inv; r.z *= inv; r.w *= inv;
            z[h * (IN / 4) + lane + 32 * v] = r;
        }
    if (ZC > 4 * IN) {
        const float4* xi = (const float4*)(x + (size_t)i * IN);
        #pragma unroll
        for (int v = 0; v < V; v++)
            z[IN + lane + 32 * v] = xi[lane + 32 * v];
    }
}

// ------------------------------------------------- stacked weight builders
__global__ void k_wstack0(const float* __restrict__ W0,
                          const float* __restrict__ skipW0) {
    int t = blockIdx.x * blockDim.x + threadIdx.x;
    if (t >= 640 * 256) return;
    int rr = t >> 8, d = t & 255;
    float v;
    if (rr < 512) { int h = rr >> 7, c = rr & 127; v = W0[c * 1024 + h * 256 + d]; }
    else          { int c = rr - 512;              v = skipW0[c * 256 + d]; }
    g_wb[t] = v;
}
__global__ void k_wstack1(const float* __restrict__ W1) {
    int t = blockIdx.x * blockDim.x + threadIdx.x;
    if (t >= 1024 * 256) return;
    int rr = t >> 8, d = t & 255;
    int h = rr >> 8, c = rr & 255;
    g_wb[t] = W1[c * 1024 + h * 256 + d];
}

// ----------------------------------------------------- bf16-split MMA GEMM
__device__ __forceinline__ uint32_t pack_bf16(float lo_elem, float hi_elem) {
    uint32_t r;
    asm("cvt.rn.bf16x2.f32 %0, %1, %2;" : "=r"(r) : "f"(hi_elem), "f"(lo_elem));
    return r;
}
// word holds (f0 -> lower 16 = element k, f1 -> upper 16 = element k+1)
__device__ __forceinline__ void split_pair(float f0, float f1,
                                           uint32_t& hw, uint32_t& lw) {
    hw = pack_bf16(f0, f1);
    float h0 = __uint_as_float(hw << 16);
    float h1 = __uint_as_float(hw & 0xffff0000u);
    lw = pack_bf16(f0 - h0, f1 - h1);
}
__device__ __forceinline__ void mma_bf16(float* c, const uint32_t* a, const uint32_t* b) {
    asm volatile(
        "mma.sync.aligned.m16n8k16.row.col.f32.bf16.bf16.f32 "
        "{%0,%1,%2,%3}, {%4,%5,%6,%7}, {%8,%9}, {%0,%1,%2,%3};"
        : "+f"(c[0]), "+f"(c[1]), "+f"(c[2]), "+f"(c[3])
        : "r"(a[0]), "r"(a[1]), "r"(a[2]), "r"(a[3]), "r"(b[0]), "r"(b[1]));
}

// C = relu(A@B + b (+b2) (+g_h residual)).  A: g_y [M,K]. B: g_wb [K,N].
// Tile 64(M) x 128(N) x 32(K). 256 threads, 8 warps (2m x 4n), warp 32x32.
// Smem: A hi/lo as bf16x2 words [64][AW]; B as vertical k-pair words [16][BW].
#define AW 20    // words per A row (16 data + 4 pad); 20 mod 32 spreads banks
#define BW 136   // words per B pair-row (128 data + 8 pad); 136 % 32 == 8
__global__ void __launch_bounds__(256, 3) k_mma(const float* __restrict__ b,
                                                const float* __restrict__ b2,
                                                int add_sel,
                                                float* __restrict__ out_ext, int out_sel,
                                                int M, int N, int K) {
    __shared__ uint32_t Ah[64 * AW], Al[64 * AW];
    __shared__ uint32_t Bh[16 * BW], Bl[16 * BW];
    const float* A = g_y;
    const float* B = g_wb;
    float* C = out_sel ? out_ext : g_h;

    int tid = threadIdx.x;
    int wid = tid >> 5, lane = tid & 31;
    int g   = lane >> 2;
    int tig = lane & 3;
    int warp_m = (wid >> 2) * 32;
    int warp_n = (wid & 3) * 32;
    int m0 = blockIdx.y * 64;
    int n0 = blockIdx.x * 128;

    float acc[2][4][4];
    #pragma unroll
    for (int i = 0; i < 2; i++)
        #pragma unroll
        for (int j = 0; j < 4; j++)
            #pragma unroll
            for (int q = 0; q < 4; q++) acc[i][j][q] = 0.f;

    // A loader: thread -> row tid/4 (0..63), k-segment (tid%4)*8
    int arow = tid >> 2;
    int akseg = (tid & 3) * 8;
    bool a_ok = (m0 + arow) < M;
    // B loader: thread -> pair rows (tid/32, tid/32+8), n = (tid%32)*4
    int bp = tid >> 5;
    int bn = (tid & 31) * 4;

    for (int k0 = 0; k0 < K; k0 += 32) {
        // ---- A tile: 64x32 fp32 -> split bf16 hi/lo packed words ----
        {
            float f[8];
            if (a_ok) {
                const float4* Ap = (const float4*)(A + (size_t)(m0 + arow) * K + k0 + akseg);
                float4 v0 = Ap[0], v1 = Ap[1];
                f[0]=v0.x; f[1]=v0.y; f[2]=v0.z; f[3]=v0.w;
                f[4]=v1.x; f[5]=v1.y; f[6]=v1.z; f[7]=v1.w;
            } else {
                #pragma unroll
                for (int j = 0; j < 8; j++) f[j] = 0.f;
            }
            uint32_t hw[4], lw[4];
            #pragma unroll
            for (int j = 0; j < 4; j++) split_pair(f[2*j], f[2*j+1], hw[j], lw[j]);
            int base = arow * AW + (akseg >> 1);
            *(uint4*)&Ah[base] = make_uint4(hw[0], hw[1], hw[2], hw[3]);
            *(uint4*)&Al[base] = make_uint4(lw[0], lw[1], lw[2], lw[3]);
        }
        // ---- B tile: 32x128 fp32 -> vertical k-pair bf16 words ----
        #pragma unroll
        for (int pp = 0; pp < 2; pp++) {
            int p = bp + 8 * pp;
            const float* B0 = B + (size_t)(k0 + 2 * p) * N + n0 + bn;
            float4 r0 = *(const float4*)B0;
            float4 r1 = *(const float4*)(B0 + N);
            uint32_t hw[4], lw[4];
            split_pair(r0.x, r1.x, hw[0], lw[0]);
            split_pair(r0.y, r1.y, hw[1], lw[1]);
            split_pair(r0.z, r1.z, hw[2], lw[2]);
            split_pair(r0.w, r1.w, hw[3], lw[3]);
            int base = p * BW + bn;
            *(uint4*)&Bh[base] = make_uint4(hw[0], hw[1], hw[2], hw[3]);
            *(uint4*)&Bl[base] = make_uint4(lw[0], lw[1], lw[2], lw[3]);
        }
        __syncthreads();

        #pragma unroll
        for (int kk2 = 0; kk2 < 2; kk2++) {       // two k16 steps
            int K0 = kk2 * 8;
            #pragma unroll
            for (int mt = 0; mt < 2; mt++) {
                int mr = warp_m + mt * 16 + g;
                uint32_t ah[4], al[4];
                ah[0] = Ah[(mr)     * AW + K0 + tig];
                ah[1] = Ah[(mr + 8) * AW + K0 + tig];
                ah[2] = Ah[(mr)     * AW + K0 + 4 + tig];
                ah[3] = Ah[(mr + 8) * AW + K0 + 4 + tig];
                al[0] = Al[(mr)     * AW + K0 + tig];
                al[1] = Al[(mr + 8) * AW + K0 + tig];
                al[2] = Al[(mr)     * AW + K0 + 4 + tig];
                al[3] = Al[(mr + 8) * AW + K0 + 4 + tig];
                #pragma unroll
                for (int nt = 0; nt < 4; nt++) {
                    int nc = warp_n + nt * 8 + g;
                    uint32_t bh[2], bl[2];
                    bh[0] = Bh[(K0 + tig)     * BW + nc];
                    bh[1] = Bh[(K0 + 4 + tig) * BW + nc];
                    bl[0] = Bl[(K0 + tig)     * BW + nc];
                    bl[1] = Bl[(K0 + 4 + tig) * BW + nc];
                    mma_bf16(acc[mt][nt], ah, bl);
                    mma_bf16(acc[mt][nt], al, bh);
                    mma_bf16(acc[mt][nt], ah, bh);
                }
            }
        }
        __syncthreads();
    }

    // ---- fused epilogue: bias (+bias2) (+residual) + relu ----
    #pragma unroll
    for (int mt = 0; mt < 2; mt++) {
        int r = m0 + warp_m + mt * 16 + g;
        #pragma unroll
        for (int nt = 0; nt < 4; nt++) {
            int cc = n0 + warp_n + nt * 8 + tig * 2;
            float bb0 = b[cc], bb1 = b[cc + 1];
            if (b2) { bb0 += b2[cc]; bb1 += b2[cc + 1]; }
            if (r < M) {
                float v0 = acc[mt][nt][0] + bb0;
                float v1 = acc[mt][nt][1] + bb1;
                if (add_sel) {
                    v0 += g_h[(size_t)r * 256 + cc];
                    v1 += g_h[(size_t)r * 256 + cc + 1];
                }
                C[(size_t)r * N + cc]     = fmaxf(v0, 0.f);
                C[(size_t)r * N + cc + 1] = fmaxf(v1, 0.f);
            }
            if (r + 8 < M) {
                float v2 = acc[mt][nt][2] + bb0;
                float v3 = acc[mt][nt][3] + bb1;
                if (add_sel) {
                    v2 += g_h[(size_t)(r + 8) * 256 + cc];
                    v3 += g_h[(size_t)(r + 8) * 256 + cc + 1];
                }
                C[(size_t)(r + 8) * N + cc]     = fmaxf(v2, 0.f);
                C[(size_t)(r + 8) * N + cc + 1] = fmaxf(v3, 0.f);
            }
        }
    }
}

// -------------------------------------------------- edge_index passthrough
__global__ void k_copy_edges_f32(const int* __restrict__ ei,
                                 float* __restrict__ out, int n) {
    int t = blockIdx.x * blockDim.x + threadIdx.x;
    if (t < n) out[t] = (float)ei[t];
}

// ---------------------------------------------------------------- launcher
extern "C" void kernel_launch(void* const* d_in, const int* in_sizes, int n_in,
                              void* d_out, int out_size) {
    const float* x      = (const float*)d_in[0];
    const int*   ei     = (const int*)d_in[1];     // int32 (JAX x64 disabled)
    const float* W0     = (const float*)d_in[2];
    const float* u0     = (const float*)d_in[3];
    const float* c0     = (const float*)d_in[4];
    const float* b0     = (const float*)d_in[5];
    const float* skipW0 = (const float*)d_in[6];
    const float* skipb0 = (const float*)d_in[7];
    const float* W1     = (const float*)d_in[8];
    const float* u1     = (const float*)d_in[9];
    const float* c1     = (const float*)d_in[10];
    const float* b1     = (const float*)d_in[11];

    int N = in_sizes[0] / 128;
    int E = in_sizes[1] / 2;
    if (N > MAXN || E > MAXE) return;

    float* out = (float*)d_out;

    // CSR build
    k_init<<<(N + 255) / 256, 256>>>(N);
    k_hist<<<(E + 255) / 256, 256>>>(ei, E, N);
    k_scan<<<1, 1024>>>(N);
    k_fill<<<(E + N + 255) / 256, 256>>>(ei, E, N);

    // ---- conv0 ----
    k_wstack0<<<(640 * 256 + 255) / 256, 256>>>(W0, skipW0);
    k_nodep<<<(N * 32 + 255) / 256, 256>>>(x, 0, u0, c0, 128, N);
    k_agg_in<128, 640><<<(N * 32 + 255) / 256, 256>>>(x, 0, N);
    {   // g_h = relu(z[:,0:640] @ Wstack0 + b0 + skipb0)
        dim3 grid(256 / 128, (N + 63) / 64);
        k_mma<<<grid, 256>>>(b0, skipb0, 0, (float*)nullptr, 0, N, 256, 640);
    }

    // ---- conv1 ----
    k_wstack1<<<(1024 * 256 + 255) / 256, 256>>>(W1);
    k_nodep<<<(N * 32 + 255) / 256, 256>>>((const float*)nullptr, 1, u1, c1, 256, N);
    k_agg_in<256, 1024><<<(N * 32 + 255) / 256, 256>>>((const float*)nullptr, 1, N);
    {   // out = relu(z @ Wstack1 + b1 + g_h)
        dim3 grid(256 / 128, (N + 63) / 64);
        k_mma<<<grid, 256>>>(b1, (const float*)nullptr, 1, out, 1, N, 256, 1024);
    }

    // edge_index passthrough
    long long hElems = (long long)N * 256;
    long long rem = (long long)out_size - hElems;
    if (rem >= 2LL * E) {
        k_copy_edges_f32<<<(2 * E + 255) / 256, 256>>>(ei, out + hElems, 2 * E);
    }
}